// round 13
// baseline (speedup 1.0000x reference)
#include <cuda_runtime.h>
#include <math.h>

#define N_NODES  50000
#define N_EDGES  400000
#define NCH      16
#define MAX_DEG  64
#define TOTAL_NK (N_NODES * NCH)            // 800000
#define OUT1_OFF (N_NODES * NCH)            // 800000
#define OUT2_OFF (N_NODES * NCH * 4)        // 3200000
#define WPB      8                          // warps (=nodes) per block
#define NCOMP    13                         // s, v(3), M(9)
#define PI10     0.3141592653589793f        // pi/Rcut
#define CRBF     0.44721359549995794f       // sqrt(2/Rcut)

#define GEOM_T       100000                 // threads; each does 4 edges
#define GEOM_BLOCKS  391                    // ceil(100000/256)
#define PACK_BLOCKS  3125                   // 800000/256

typedef unsigned long long F2;

__device__ __forceinline__ F2 f2pack(float lo, float hi) {
    F2 r; asm("mov.b64 %0,{%1,%2};" : "=l"(r) : "f"(lo), "f"(hi)); return r;
}
__device__ __forceinline__ void f2unpack(F2 v, float& lo, float& hi) {
    asm("mov.b64 {%0,%1},%2;" : "=f"(lo), "=f"(hi) : "l"(v));
}
__device__ __forceinline__ F2 f2fma(F2 a, F2 b, F2 c) {
    F2 d; asm("fma.rn.f32x2 %0,%1,%2,%3;" : "=l"(d) : "l"(a), "l"(b), "l"(c)); return d;
}
__device__ __forceinline__ F2 f2add(F2 a, F2 b) {
    F2 d; asm("add.rn.f32x2 %0,%1,%2;" : "=l"(d) : "l"(a), "l"(b)); return d;
}
__device__ __forceinline__ F2 f2mul(F2 a, F2 b) {
    F2 d; asm("mul.rn.f32x2 %0,%1,%2;" : "=l"(d) : "l"(a), "l"(b)); return d;
}

// ---- scratch (__device__ globals: no allocation allowed) ----
__device__ float  g_dist[N_EDGES];
__device__ int    g_cnt[N_NODES];                 // degree by src (zero at entry, reset by gather)
__device__ float4 g_rec4[N_NODES * MAX_DEG];      // (ux,uy,uz, dst-as-bits) bucketed by src
__device__ int    g_rece[N_NODES * MAX_DEG];      // original edge id per slot
__device__ float  g_hp[N_NODES * NCOMP * NCH];    // h transposed: [n][component][k]

// fused prep: geom blocks (4 edges/thread, MLP=4) + h-transpose blocks
__global__ void prep_kernel(const float* __restrict__ pos,
                            const int* __restrict__ ei,
                            const float* __restrict__ h0,
                            const float* __restrict__ h1,
                            const float* __restrict__ h2) {
    if (blockIdx.x < GEOM_BLOCKS) {
        int t = blockIdx.x * blockDim.x + threadIdx.x;
        if (t >= GEOM_T) return;
        #pragma unroll
        for (int i = 0; i < 4; ++i) {
            int e = t + i * GEOM_T;                        // 4*100000 == N_EDGES
            int s = ei[e];
            int d = ei[N_EDGES + e];
            float rx = pos[3 * s + 0] - pos[3 * d + 0];
            float ry = pos[3 * s + 1] - pos[3 * d + 1];
            float rz = pos[3 * s + 2] - pos[3 * d + 2];
            float d2 = rx * rx + ry * ry + rz * rz;
            float inv = rsqrtf(d2);
            g_dist[e] = d2 * inv;
            int rank = atomicAdd(&g_cnt[s], 1);
            int slot = s * MAX_DEG + rank;
            g_rec4[slot] = make_float4(rx * inv, ry * inv, rz * inv, __int_as_float(d));
            g_rece[slot] = e;
        }
    } else {
        int idx = (blockIdx.x - GEOM_BLOCKS) * blockDim.x + threadIdx.x;
        if (idx >= TOTAL_NK) return;
        int n = idx >> 4;
        int k = idx & 15;
        float* o = g_hp + (n * NCOMP) * NCH + k;
        o[0] = h0[idx];
        const float* vp = h1 + (size_t)idx * 3;
        o[1 * NCH] = vp[0];
        o[2 * NCH] = vp[1];
        o[3 * NCH] = vp[2];
        const float* Mp = h2 + (size_t)idx * 9;
        #pragma unroll
        for (int c = 0; c < 9; ++c) o[(4 + c) * NCH] = Mp[c];
    }
}

// gather: ONE WARP PER NODE. Quarter-warp q handles edges 4j+q; each lane
// processes TWO channels (2*sub, 2*sub+1) packed in f32x2 registers.
__global__ void __launch_bounds__(256, 4)
gather_kernel(float* __restrict__ out) {
    __shared__ float4 sh[WPB * 52];        // epilogue staging only

    int warpid = threadIdx.x >> 5;
    int lane   = threadIdx.x & 31;
    int q      = lane >> 3;                // edge sub-index 0..3
    int sub    = lane & 7;                 // channel-pair index
    int kk     = sub * 2;                  // first channel of pair
    int n      = blockIdx.x * WPB + warpid;

    int cnt = g_cnt[n];
    int off = n * MAX_DEG;

    const F2 TWO = 0x4000000040000000ULL;  // (2.0f, 2.0f)

    F2 A0 = 0, A1x = 0, A1y = 0, A1z = 0;
    F2 A2[9] = {0,0,0,0,0,0,0,0,0};

    int jmax = (cnt + 3) >> 2;
    for (int j = 0; j < jmax; ++j) {
        int idx4 = 4 * j + q;
        bool valid = idx4 < cnt;
        int slot = off + (valid ? idx4 : 0);

        float4 rec = __ldg(&g_rec4[slot]);         // broadcast in quarter-warp
        int    e   = __ldg(&g_rece[slot]);
        int dst = __float_as_int(rec.w);

        // packed h pair loads: 13 x LDG.64, lane-contiguous
        const float2* hpp = (const float2*)(g_hp + (size_t)dst * (NCOMP * NCH)) + sub;
        float2 l0  = __ldg(hpp + 0 * 8);
        float2 l1  = __ldg(hpp + 1 * 8);
        float2 l2  = __ldg(hpp + 2 * 8);
        float2 l3  = __ldg(hpp + 3 * 8);
        float2 l4  = __ldg(hpp + 4 * 8);
        float2 l5  = __ldg(hpp + 5 * 8);
        float2 l6  = __ldg(hpp + 6 * 8);
        float2 l7  = __ldg(hpp + 7 * 8);
        float2 l8  = __ldg(hpp + 8 * 8);
        float2 l9  = __ldg(hpp + 9 * 8);
        float2 l10 = __ldg(hpp + 10 * 8);
        float2 l11 = __ldg(hpp + 11 * 8);
        float2 l12 = __ldg(hpp + 12 * 8);

        // inline radial for both channels (faithful [K,E]->[E,K] reshape quirk)
        unsigned f0 = (unsigned)e * 16u + (unsigned)kk;
        unsigned n0 = f0 / N_EDGES, e0 = f0 - n0 * N_EDGES;
        unsigned f1 = f0 + 1u;
        unsigned n1 = f1 / N_EDGES, e1 = f1 - n1 * N_EDGES;
        float rr0 = __ldg(g_dist + e0);
        float rr1 = __ldg(g_dist + e1);
        float rho0 = valid ? (CRBF * __sinf((float)(n0 + 1) * PI10 * rr0) / rr0) : 0.0f;
        float rho1 = valid ? (CRBF * __sinf((float)(n1 + 1) * PI10 * rr1) / rr1) : 0.0f;
        F2 RHO = f2pack(rho0, rho1);

        F2 UX = f2pack(rec.x, rec.x);
        F2 UY = f2pack(rec.y, rec.y);
        F2 UZ = f2pack(rec.z, rec.z);

        F2 S   = f2pack(l0.x,  l0.y);
        F2 VX  = f2pack(l1.x,  l1.y);
        F2 VY  = f2pack(l2.x,  l2.y);
        F2 VZ  = f2pack(l3.x,  l3.y);
        F2 M00 = f2pack(l4.x,  l4.y);
        F2 M01 = f2pack(l5.x,  l5.y);
        F2 M02 = f2pack(l6.x,  l6.y);
        F2 M10 = f2pack(l7.x,  l7.y);
        F2 M11 = f2pack(l8.x,  l8.y);
        F2 M12 = f2pack(l9.x,  l9.y);
        F2 M20 = f2pack(l10.x, l10.y);
        F2 M21 = f2pack(l11.x, l11.y);
        F2 M22 = f2pack(l12.x, l12.y);

        F2 vd  = f2fma(VX, UX, f2fma(VY, UY, f2mul(VZ, UZ)));
        F2 tr  = f2add(M00, f2add(M11, M22));
        F2 Mux = f2fma(M00, UX, f2fma(M01, UY, f2mul(M02, UZ)));
        F2 Muy = f2fma(M10, UX, f2fma(M11, UY, f2mul(M12, UZ)));
        F2 Muz = f2fma(M20, UX, f2fma(M21, UY, f2mul(M22, UZ)));
        F2 Mtux = f2fma(M00, UX, f2fma(M10, UY, f2mul(M20, UZ)));
        F2 Mtuy = f2fma(M01, UX, f2fma(M11, UY, f2mul(M21, UZ)));
        F2 Mtuz = f2fma(M02, UX, f2fma(M12, UY, f2mul(M22, UZ)));
        F2 uMu = f2fma(UX, Mux, f2fma(UY, Muy, f2mul(UZ, Muz)));

        // out0 += rho*(2s + vd + 2(tr + uMu))
        F2 t0 = f2fma(TWO, S, vd);
        t0 = f2fma(TWO, f2add(tr, uMu), t0);
        A0 = f2fma(RHO, t0, A0);

        F2 str = f2add(S, tr);
        F2 c1  = f2mul(RHO, f2fma(TWO, vd, str));
        F2 ct  = f2mul(RHO, str);

        F2 mx = f2add(Mux, Mtux);
        F2 my = f2add(Muy, Mtuy);
        F2 mz = f2add(Muz, Mtuz);

        // out1_c += c1*u_c + rho*(2v_c + m_c)
        A1x = f2fma(c1, UX, f2fma(RHO, f2fma(TWO, VX, mx), A1x));
        A1y = f2fma(c1, UY, f2fma(RHO, f2fma(TWO, VY, my), A1y));
        A1z = f2fma(c1, UZ, f2fma(RHO, f2fma(TWO, VZ, mz), A1z));

        // a_c = ct*u_c + rho*(v_c + 2*m_c);  out2_ij += 2rho*M_ij + a_i u_j
        F2 ax = f2fma(ct, UX, f2mul(RHO, f2fma(TWO, mx, VX)));
        F2 ay = f2fma(ct, UY, f2mul(RHO, f2fma(TWO, my, VY)));
        F2 az = f2fma(ct, UZ, f2mul(RHO, f2fma(TWO, mz, VZ)));
        F2 r2m = f2mul(TWO, RHO);
        A2[0] = f2fma(r2m, M00, f2fma(ax, UX, A2[0]));
        A2[1] = f2fma(r2m, M01, f2fma(ax, UY, A2[1]));
        A2[2] = f2fma(r2m, M02, f2fma(ax, UZ, A2[2]));
        A2[3] = f2fma(r2m, M10, f2fma(ay, UX, A2[3]));
        A2[4] = f2fma(r2m, M11, f2fma(ay, UY, A2[4]));
        A2[5] = f2fma(r2m, M12, f2fma(ay, UZ, A2[5]));
        A2[6] = f2fma(r2m, M20, f2fma(az, UX, A2[6]));
        A2[7] = f2fma(r2m, M21, f2fma(az, UY, A2[7]));
        A2[8] = f2fma(r2m, M22, f2fma(az, UZ, A2[8]));
    }

    // reduce across the 4 quarter-warps (same channel pair, disjoint edges)
    const unsigned FULL = 0xffffffffu;
    #define RED(X) X = f2add(X, __shfl_xor_sync(FULL, X, 8)); \
                   X = f2add(X, __shfl_xor_sync(FULL, X, 16))
    RED(A0); RED(A1x); RED(A1y); RED(A1z);
    #pragma unroll
    for (int c = 0; c < 9; ++c) { RED(A2[c]); }
    #undef RED

    // staging: lanes 0..7 unpack their channel pair into the 52-float4 layout
    float* w = (float*)(sh + warpid * 52);
    if (lane < 8) {
        int k0 = kk, k1 = kk + 1;
        float lo, hi;
        f2unpack(A0, lo, hi);  w[k0] = lo;  w[k1] = hi;
        f2unpack(A1x, lo, hi); w[16 + 3 * k0 + 0] = lo; w[16 + 3 * k1 + 0] = hi;
        f2unpack(A1y, lo, hi); w[16 + 3 * k0 + 1] = lo; w[16 + 3 * k1 + 1] = hi;
        f2unpack(A1z, lo, hi); w[16 + 3 * k0 + 2] = lo; w[16 + 3 * k1 + 2] = hi;
        #pragma unroll
        for (int c = 0; c < 9; ++c) {
            f2unpack(A2[c], lo, hi);
            w[64 + 9 * k0 + c] = lo;
            w[64 + 9 * k1 + c] = hi;
        }
    }
    __syncwarp();

    const float4* rd = sh + warpid * 52;      // 52 f4 = {out0row, out1row, out2row}
    float4* O0 = (float4*)(out + (size_t)n * 16);
    float4* O1 = (float4*)(out + OUT1_OFF + (size_t)n * 48);
    float4* O2 = (float4*)(out + OUT2_OFF + (size_t)n * 144);
    {
        float4 val = rd[lane];
        float4* p = (lane < 4) ? (O0 + lane)
                  : ((lane < 16) ? (O1 + lane - 4) : (O2 + lane - 16));
        *p = val;
    }
    {
        int t = lane + 32;                     // 32..51
        if (t < 52) O2[t - 16] = rd[t];
    }

    if (lane == 0) g_cnt[n] = 0;               // reset for next launch
}

extern "C" void kernel_launch(void* const* d_in, const int* in_sizes, int n_in,
                              void* d_out, int out_size) {
    const float* h0  = (const float*)d_in[0];
    const float* h1  = (const float*)d_in[1];
    const float* h2  = (const float*)d_in[2];
    const float* pos = (const float*)d_in[3];
    // d_in[4] = channel_weights (provably unused by reference output)
    const int*   ei  = (const int*)d_in[5];
    float* out = (float*)d_out;

    prep_kernel<<<GEOM_BLOCKS + PACK_BLOCKS, 256>>>(pos, ei, h0, h1, h2);
    gather_kernel<<<N_NODES / WPB, 32 * WPB>>>(out);
}